// round 3
// baseline (speedup 1.0000x reference)
#include <cuda_runtime.h>
#include <math.h>

#define NF 128
#define NH 128
#define NK 5
#define NMAX 10000
#define TE 16        // edges per tile
#define ST 20        // padded staging stride (floats)

// ---------------- device scratch (no allocations allowed) ----------------
__device__ float g_P[NMAX * NH];   // h@cw1[0:128]   + na@cw1[256:384]
__device__ float g_Q[NMAX * NH];   // h@cw1[128:256] + na@cw1[384:512]
__device__ int   g_is64;

__constant__ float c_scales[15] = {
    -0.5f,
    -0.222222222f,
    -0.0987654321f,
    -0.0438957476f,
    -0.0195092212f,
    -0.00867076500f,
    -0.00385367333f,
    -0.00171274370f,
    -0.000761219424f,
    -0.000338319744f,
    -0.000150364331f,
    -6.68285914e-05f,
    -2.97015962e-05f,
    -1.32007094e-05f,
    -5.86698196e-06f
};

__device__ __forceinline__ float siluf(float x) {
    return __fdividef(x, 1.0f + __expf(-x));
}
__device__ __forceinline__ float sigmoidf(float x) {
    return __fdividef(1.0f, 1.0f + __expf(-x));
}

// ---------------- kernel 0: int64 vs int32 edge dtype detection ----------------
// Indices are < 10000, so if edges are int64 every odd 32-bit word is 0.
__global__ void detect_kernel(const int* __restrict__ e32, int nprobe) {
    __shared__ int nz;
    if (threadIdx.x == 0) nz = 0;
    __syncthreads();
    int local = 0;
    for (int i = threadIdx.x; i < nprobe; i += blockDim.x)
        if (e32[2 * i + 1] != 0) local = 1;
    if (local) atomicOr(&nz, 1);
    __syncthreads();
    if (threadIdx.x == 0) g_is64 = (nz == 0) ? 1 : 0;
}

// ---------------- kernel 1: node-level folding of cw1 ----------------
// P[n][j] = sum_k h[n][k]*cw1[k][j]      + na[n][k]*cw1[256+k][j]
// Q[n][j] = sum_k h[n][k]*cw1[128+k][j]  + na[n][k]*cw1[384+k][j]
__global__ __launch_bounds__(128) void node_pre(
    const float* __restrict__ h, const float* __restrict__ na,
    const float* __restrict__ cw1, int N)
{
    __shared__ float hs[16][128];
    __shared__ float nas[16][128];
    int n0 = blockIdx.x * 16;
    int tid = threadIdx.x;   // 128 threads, thread = output column j

    for (int idx = tid; idx < 16 * 128; idx += 128) {
        int n = idx >> 7, k = idx & 127;
        int gn = n0 + n;
        hs[n][k]  = (gn < N) ? h[(size_t)gn * 128 + k]  : 0.0f;
        nas[n][k] = (gn < N) ? na[(size_t)gn * 128 + k] : 0.0f;
    }
    __syncthreads();

    int j = tid;
    float accP[16], accQ[16];
#pragma unroll
    for (int n = 0; n < 16; n++) { accP[n] = 0.0f; accQ[n] = 0.0f; }

    for (int k = 0; k < 128; k++) {
        float whr = cw1[(size_t)k * 128 + j];
        float whc = cw1[(size_t)(128 + k) * 128 + j];
        float wnr = cw1[(size_t)(256 + k) * 128 + j];
        float wnc = cw1[(size_t)(384 + k) * 128 + j];
#pragma unroll
        for (int n = 0; n < 16; n++) {
            float hv = hs[n][k], nav = nas[n][k];
            accP[n] = fmaf(hv, whr, fmaf(nav, wnr, accP[n]));
            accQ[n] = fmaf(hv, whc, fmaf(nav, wnc, accQ[n]));
        }
    }
#pragma unroll
    for (int n = 0; n < 16; n++) {
        int gn = n0 + n;
        if (gn < N) {
            g_P[(size_t)gn * 128 + j] = accP[n];
            g_Q[(size_t)gn * 128 + j] = accQ[n];
        }
    }
}

// ---------------- kernel 2: persistent fused edge kernel ----------------
// Split-warp GEMV: warps 0-3 chem path, warps 4-7 pos path (4 edges/warp).
// smem (floats): cw2 16384 | pw2 16384 | sw 16384 | pw1 2560 |
//                a1s 128*ST | u1s 128*ST | 6 biases*128 | posin TE*20 | ab | idx
#define SMEM_FLOATS (3 * 16384 + 2560 + 128 * ST + 128 * ST + 6 * 128 + TE * 20 + 1)
#define SMEM_BYTES  (SMEM_FLOATS * 4 + 2 * TE * 4)

__global__ __launch_bounds__(256, 1) void edge_kernel(
    const float* __restrict__ coord, const float* __restrict__ nvecs,
    const float* __restrict__ cw2g,  const float* __restrict__ pw1g,
    const float* __restrict__ pw2g,  const float* __restrict__ swg,
    const float* __restrict__ cb1g,  const float* __restrict__ cb2g,
    const float* __restrict__ pb1g,  const float* __restrict__ pb2g,
    const float* __restrict__ sbg,   const float* __restrict__ awg,
    const float* __restrict__ abg,
    const void* __restrict__ edges, int E,
    float* __restrict__ out)
{
    extern __shared__ float sm[];
    float* Wc   = sm;                 // cw2  [128][128]
    float* Wp2  = Wc + 16384;         // pw2  [128][128]
    float* Wsw  = Wp2 + 16384;        // sw   [128][128]
    float* Wp1  = Wsw + 16384;        // pw1  [20][128]
    float* a1s  = Wp1 + 2560;         // [128][ST] transposed acts (then chem staged)
    float* u1s  = a1s + 128 * ST;     // [128][ST] (then pos staged row-major [16][128])
    float* cb1s = u1s + 128 * ST;
    float* cb2s = cb1s + 128;
    float* pb1s = cb2s + 128;
    float* pb2s = pb1s + 128;
    float* sbs  = pb2s + 128;
    float* aws  = sbs + 128;
    float* posin = aws + 128;         // [TE][20]
    float* abp  = posin + TE * 20;
    int*   rows = (int*)(abp + 1);
    int*   cols = rows + TE;

    const int tid = threadIdx.x;

    // one-time weight load into smem
    for (int i = tid; i < 16384; i += 256) {
        Wc[i]  = cw2g[i];
        Wp2[i] = pw2g[i];
        Wsw[i] = swg[i];
    }
    for (int i = tid; i < 2560; i += 256) Wp1[i] = pw1g[i];
    if (tid < 128) {
        cb1s[tid] = cb1g[tid]; cb2s[tid] = cb2g[tid];
        pb1s[tid] = pb1g[tid]; pb2s[tid] = pb2g[tid];
        sbs[tid]  = sbg[tid];  aws[tid]  = awg[tid];
    }
    if (tid == 0) *abp = abg[0];
    const int is64 = g_is64;
    __syncthreads();

    const float abv = *abp;
    const size_t chemO = (size_t)E * 128;
    const size_t posO  = (size_t)E * 256;
    const size_t cdO   = (size_t)E * 384;

    const int warp = tid >> 5;
    const int lane = tid & 31;
    const int eb   = (warp & 3) * 4;   // 4 edges per warp
    const int c0   = lane * 4;         // 4 output cols per lane
    const bool isChem = warp < 4;

    const int nTiles = (E + TE - 1) / TE;
    for (int t = blockIdx.x; t < nTiles; t += gridDim.x) {
        const int base = t * TE;
        const int nE = min(TE, E - base);
        __syncthreads();   // protect smem staging across tile iterations

        // ---- Phase A: per-edge geometry (cd, radial, nprod) ----
        if (tid < nE) {
            const int e = tid;
            const size_t ge = (size_t)base + e;
            int r, c;
            if (is64) {
                const long long* e64 = (const long long*)edges;
                r = (int)e64[ge]; c = (int)e64[(size_t)E + ge];
            } else {
                const int* e32i = (const int*)edges;
                r = e32i[ge]; c = e32i[(size_t)E + ge];
            }
            rows[e] = r; cols[e] = c;
            float dx = coord[r * 3 + 0] - coord[c * 3 + 0];
            float dy = coord[r * 3 + 1] - coord[c * 3 + 1];
            float dz = coord[r * 3 + 2] - coord[c * 3 + 2];
            float nrm = sqrtf(dx * dx + dy * dy + dz * dz);
            float inv = __fdividef(1.0f, nrm + 1e-8f);
            float cx = dx * inv, cy = dy * inv, cz = dz * inv;
            out[cdO + ge * 3 + 0] = cx;
            out[cdO + ge * 3 + 1] = cy;
            out[cdO + ge * 3 + 2] = cz;
            float ir = cx * cx + cy * cy + cz * cz;
#pragma unroll
            for (int s = 0; s < 15; s++)
                posin[e * 20 + 5 + s] = __expf(ir * c_scales[s]);
#pragma unroll
            for (int k2 = 0; k2 < NK; k2++) {
                const float* av = &nvecs[((size_t)r * NK + k2) * 3];
                const float* bv = &nvecs[((size_t)c * NK + k2) * 3];
                posin[e * 20 + k2] = av[0] * bv[0] + av[1] * bv[1] + av[2] * bv[2];
            }
        }
        __syncthreads();

        // ---- Phase B: a1 = silu(P[row] + Q[col] + cb1), transposed ----
        for (int idx = tid; idx < nE * 128; idx += 256) {
            int e = idx >> 7, k = idx & 127;
            int r = rows[e], c = cols[e];
            float v = g_P[(size_t)r * 128 + k] + g_Q[(size_t)c * 128 + k] + cb1s[k];
            a1s[k * ST + e] = siluf(v);
        }
        // ---- Phase B2: u1 = silu(pos_in @ pw1 + pb1), transposed ----
        for (int idx = tid; idx < nE * 128; idx += 256) {
            int e = idx >> 7, j = idx & 127;
            float acc = pb1s[j];
#pragma unroll
            for (int k = 0; k < 20; k++)
                acc = fmaf(posin[e * 20 + k], Wp1[k * 128 + j], acc);
            u1s[j * ST + e] = siluf(acc);
        }
        __syncthreads();

        // ---- Phase C: split-warp GEMV.
        //      warps 0-3:  chem = silu(a1 @ cw2 + cb2)   (4 edges each)
        //      warps 4-7:  pos  = silu(u1 @ pw2 + pb2)
        const float* W    = isChem ? Wc   : Wp2;
        const float* X    = isChem ? a1s  : u1s;
        const float* bias = isChem ? cb2s : pb2s;

        float acc[4][4];
#pragma unroll
        for (int e = 0; e < 4; e++)
#pragma unroll
            for (int q = 0; q < 4; q++) acc[e][q] = bias[c0 + q];

#pragma unroll 4
        for (int k = 0; k < 128; k++) {
            float4 w = *(const float4*)(W + k * 128 + c0);
            float4 x = *(const float4*)(X + k * ST + eb);   // 4 edges, broadcast
            acc[0][0] = fmaf(x.x, w.x, acc[0][0]);
            acc[0][1] = fmaf(x.x, w.y, acc[0][1]);
            acc[0][2] = fmaf(x.x, w.z, acc[0][2]);
            acc[0][3] = fmaf(x.x, w.w, acc[0][3]);
            acc[1][0] = fmaf(x.y, w.x, acc[1][0]);
            acc[1][1] = fmaf(x.y, w.y, acc[1][1]);
            acc[1][2] = fmaf(x.y, w.z, acc[1][2]);
            acc[1][3] = fmaf(x.y, w.w, acc[1][3]);
            acc[2][0] = fmaf(x.z, w.x, acc[2][0]);
            acc[2][1] = fmaf(x.z, w.y, acc[2][1]);
            acc[2][2] = fmaf(x.z, w.z, acc[2][2]);
            acc[2][3] = fmaf(x.z, w.w, acc[2][3]);
            acc[3][0] = fmaf(x.w, w.x, acc[3][0]);
            acc[3][1] = fmaf(x.w, w.y, acc[3][1]);
            acc[3][2] = fmaf(x.w, w.z, acc[3][2]);
            acc[3][3] = fmaf(x.w, w.w, acc[3][3]);
        }

        float val[4][4];
#pragma unroll
        for (int e = 0; e < 4; e++)
#pragma unroll
            for (int q = 0; q < 4; q++)
                val[e][q] = siluf(acc[e][q]);

        // write chem / pos to gmem
        const size_t oBase = isChem ? chemO : posO;
#pragma unroll
        for (int e = 0; e < 4; e++) {
            int ee = eb + e;
            if (ee < nE) {
                size_t ge = (size_t)base + ee;
                *(float4*)(out + oBase + ge * 128 + c0) =
                    make_float4(val[e][0], val[e][1], val[e][2], val[e][3]);
            }
        }
        __syncthreads();   // all Phase C reads of a1s/u1s done

        // ---- stage: chem -> a1s transposed [k][e]; pos -> u1s row-major [e][128]
        if (isChem) {
#pragma unroll
            for (int e = 0; e < 4; e++)
#pragma unroll
                for (int q = 0; q < 4; q++)
                    a1s[(c0 + q) * ST + eb + e] = val[e][q];
        } else {
#pragma unroll
            for (int e = 0; e < 4; e++)
                *(float4*)(u1s + (eb + e) * 128 + c0) =
                    make_float4(val[e][0], val[e][1], val[e][2], val[e][3]);
        }
        __syncthreads();

        // ---- Phase D: warps 0-3 gate GEMV g = silu(chem@sw+sb); out0 = g*pos;
        //      attention sigmoid gate; final store.
        if (isChem) {
            float g[4][4];
#pragma unroll
            for (int e = 0; e < 4; e++)
#pragma unroll
                for (int q = 0; q < 4; q++) g[e][q] = sbs[c0 + q];
#pragma unroll 4
            for (int k = 0; k < 128; k++) {
                float4 w = *(const float4*)(Wsw + k * 128 + c0);
                float4 x = *(const float4*)(a1s + k * ST + eb);
                g[0][0] = fmaf(x.x, w.x, g[0][0]);
                g[0][1] = fmaf(x.x, w.y, g[0][1]);
                g[0][2] = fmaf(x.x, w.z, g[0][2]);
                g[0][3] = fmaf(x.x, w.w, g[0][3]);
                g[1][0] = fmaf(x.y, w.x, g[1][0]);
                g[1][1] = fmaf(x.y, w.y, g[1][1]);
                g[1][2] = fmaf(x.y, w.z, g[1][2]);
                g[1][3] = fmaf(x.y, w.w, g[1][3]);
                g[2][0] = fmaf(x.z, w.x, g[2][0]);
                g[2][1] = fmaf(x.z, w.y, g[2][1]);
                g[2][2] = fmaf(x.z, w.z, g[2][2]);
                g[2][3] = fmaf(x.z, w.w, g[2][3]);
                g[3][0] = fmaf(x.w, w.x, g[3][0]);
                g[3][1] = fmaf(x.w, w.y, g[3][1]);
                g[3][2] = fmaf(x.w, w.z, g[3][2]);
                g[3][3] = fmaf(x.w, w.w, g[3][3]);
            }
            float aw0 = aws[c0 + 0], aw1 = aws[c0 + 1];
            float aw2 = aws[c0 + 2], aw3 = aws[c0 + 3];
#pragma unroll
            for (int e = 0; e < 4; e++) {
                float4 pv = *(const float4*)(u1s + (eb + e) * 128 + c0);
                float o0 = siluf(g[e][0]) * pv.x;
                float o1 = siluf(g[e][1]) * pv.y;
                float o2 = siluf(g[e][2]) * pv.z;
                float o3 = siluf(g[e][3]) * pv.w;
                float part = o0 * aw0 + o1 * aw1 + o2 * aw2 + o3 * aw3;
                part += __shfl_xor_sync(0xffffffffu, part, 16);
                part += __shfl_xor_sync(0xffffffffu, part, 8);
                part += __shfl_xor_sync(0xffffffffu, part, 4);
                part += __shfl_xor_sync(0xffffffffu, part, 2);
                part += __shfl_xor_sync(0xffffffffu, part, 1);
                float att = sigmoidf(part + abv);
                int ee = eb + e;
                if (ee < nE) {
                    size_t ge = (size_t)base + ee;
                    *(float4*)(out + ge * 128 + c0) =
                        make_float4(o0 * att, o1 * att, o2 * att, o3 * att);
                }
            }
        }
    }
}

// ---------------- launch ----------------
extern "C" void kernel_launch(void* const* d_in, const int* in_sizes, int n_in,
                              void* d_out, int out_size) {
    const float* h     = (const float*)d_in[0];
    const float* coord = (const float*)d_in[1];
    const float* nvecs = (const float*)d_in[2];
    const float* na    = (const float*)d_in[3];
    const float* cw1   = (const float*)d_in[4];
    const float* cb1   = (const float*)d_in[5];
    const float* cw2   = (const float*)d_in[6];
    const float* cb2   = (const float*)d_in[7];
    const float* pw1   = (const float*)d_in[8];
    const float* pb1   = (const float*)d_in[9];
    const float* pw2   = (const float*)d_in[10];
    const float* pb2   = (const float*)d_in[11];
    const float* sw    = (const float*)d_in[12];
    const float* sb    = (const float*)d_in[13];
    const float* aw    = (const float*)d_in[14];
    const float* ab    = (const float*)d_in[15];
    const void*  edges = d_in[16];

    const int N = in_sizes[0] / NF;
    // out = (out[E,128], chem[E,128], pos[E,128], cd[E,3]) -> 387 floats/edge.
    const int E = out_size / 387;
    float* out = (float*)d_out;

    cudaFuncSetAttribute(edge_kernel,
                         cudaFuncAttributeMaxDynamicSharedMemorySize, SMEM_BYTES);

    int nprobe = (E < 1024) ? E : 1024;
    detect_kernel<<<1, 256>>>((const int*)edges, nprobe);
    node_pre<<<(N + 15) / 16, 128>>>(h, na, cw1, N);

    const int nTiles = (E + TE - 1) / TE;
    const int grid = nTiles < 148 ? nTiles : 148;
    edge_kernel<<<grid, 256, SMEM_BYTES>>>(
        coord, nvecs, cw2, pw1, pw2, sw,
        cb1, cb2, pb1, pb2, sb, aw, ab,
        edges, E, out);
}

// round 7
// speedup vs baseline: 2.5992x; 2.5992x over previous
#include <cuda_runtime.h>
#include <cuda_fp16.h>
#include <stdint.h>

#define NF 128
#define NMAX 10000
#define THREADS 256
#define TE 64

// ===================== scratch =====================
__device__ float g_P[NMAX * NF];
__device__ float g_Q[NMAX * NF];
__device__ int   g_is64;
// weight blob: fp16 [n][k] images, padded strides (272B big, 80B pw1)
#define WB_WC   0
#define WB_WP2  34816
#define WB_WS   69632
#define WB_WP1  104448
#define WBLOB_BYTES 114688
__device__ unsigned char g_wb[WBLOB_BYTES];

// smem map (bytes)
#define SM_WC   0
#define SM_WP2  34816
#define SM_WS   69632
#define SM_WP1  104448
#define SM_AHI  114688   // 64 x 272
#define SM_ALO  132096
#define SM_UHI  149504
#define SM_ULO  166912
#define SM_PHI  184320   // 64 x 80
#define SM_PLO  189440
#define SM_CB1  194560
#define SM_CB2  195072
#define SM_PB1  195584
#define SM_PB2  196096
#define SM_SB   196608
#define SM_AW   197120
#define SM_ATT  197632   // 4*64 floats
#define SM_ROWS 198656
#define SM_COLS 198912
#define SM_AB   199168
#define SMEM_BYTES 199200

__constant__ float c_scales[15] = {
    -0.5f, -0.222222222f, -0.0987654321f, -0.0438957476f, -0.0195092212f,
    -0.00867076500f, -0.00385367333f, -0.00171274370f, -0.000761219424f,
    -0.000338319744f, -0.000150364331f, -6.68285914e-05f, -2.97015962e-05f,
    -1.32007094e-05f, -5.86698196e-06f
};

__device__ __forceinline__ float siluf(float x) {
    return __fdividef(x, 1.0f + __expf(-x));
}
__device__ __forceinline__ float sigmoidf(float x) {
    return __fdividef(1.0f, 1.0f + __expf(-x));
}
__device__ __forceinline__ uint32_t smem_u32(const void* p) {
    uint32_t a;
    asm("{ .reg .u64 t; cvta.to.shared.u64 t, %1; cvt.u32.u64 %0, t; }" : "=r"(a) : "l"(p));
    return a;
}
__device__ __forceinline__ void ldsm4(uint32_t addr, uint32_t* r) {
    asm volatile("ldmatrix.sync.aligned.m8n8.x4.shared.b16 {%0,%1,%2,%3}, [%4];"
        : "=r"(r[0]), "=r"(r[1]), "=r"(r[2]), "=r"(r[3]) : "r"(addr));
}
__device__ __forceinline__ void mma16816(float* c, const uint32_t* a, uint32_t b0, uint32_t b1) {
    asm volatile(
        "mma.sync.aligned.m16n8k16.row.col.f32.f16.f16.f32 "
        "{%0,%1,%2,%3},{%4,%5,%6,%7},{%8,%9},{%0,%1,%2,%3};"
        : "+f"(c[0]), "+f"(c[1]), "+f"(c[2]), "+f"(c[3])
        : "r"(a[0]), "r"(a[1]), "r"(a[2]), "r"(a[3]), "r"(b0), "r"(b1));
}

// 2-pass (A hi/lo) 64xNx(16*nks) GEMM into acc[8][4]; warp (mw,nw) owns 32x32.
__device__ __forceinline__ void gemm_tile(
    uint32_t aHi, uint32_t aLo, uint32_t strA,
    uint32_t bBase, uint32_t strB, int nks,
    int mw, int nw, int lane, float acc[8][4])
{
    const uint32_t aoff = (uint32_t)(mw * 32 + (lane & 15)) * strA + (uint32_t)(lane >> 4) * 16;
    const uint32_t boff = (uint32_t)(nw * 32 + (lane & 15)) * strB + (uint32_t)(lane >> 4) * 16;
#pragma unroll
    for (int pass = 0; pass < 2; pass++) {
        uint32_t abase = (pass ? aLo : aHi) + aoff;
        uint32_t bbase = bBase + boff;
        for (int ks = 0; ks < nks; ks++) {
            uint32_t a0[4], a1[4], b0[4], b1[4];
            ldsm4(abase + ks * 32, a0);
            ldsm4(abase + 16 * strA + ks * 32, a1);
            ldsm4(bbase + ks * 32, b0);
            ldsm4(bbase + 16 * strB + ks * 32, b1);
            mma16816(acc[0], a0, b0[0], b0[2]);
            mma16816(acc[1], a0, b0[1], b0[3]);
            mma16816(acc[2], a0, b1[0], b1[2]);
            mma16816(acc[3], a0, b1[1], b1[3]);
            mma16816(acc[4], a1, b0[0], b0[2]);
            mma16816(acc[5], a1, b0[1], b0[3]);
            mma16816(acc[6], a1, b1[0], b1[2]);
            mma16816(acc[7], a1, b1[1], b1[3]);
        }
    }
}

// ===================== kernel 0: edge dtype detection =====================
__global__ void detect_kernel(const int* __restrict__ e32, int nprobe) {
    __shared__ int nz;
    if (threadIdx.x == 0) nz = 0;
    __syncthreads();
    int local = 0;
    for (int i = threadIdx.x; i < nprobe; i += blockDim.x)
        if (e32[2 * i + 1] != 0) local = 1;
    if (local) atomicOr(&nz, 1);
    __syncthreads();
    if (threadIdx.x == 0) g_is64 = (nz == 0) ? 1 : 0;
}

// ===================== kernel 1: fold cw1 into per-node P/Q =====================
__global__ __launch_bounds__(128) void node_pre(
    const float* __restrict__ h, const float* __restrict__ na,
    const float* __restrict__ cw1, int N)
{
    __shared__ float hs[16][128];
    __shared__ float nas[16][128];
    int n0 = blockIdx.x * 16;
    int tid = threadIdx.x;
    for (int idx = tid; idx < 16 * 128; idx += 128) {
        int n = idx >> 7, k = idx & 127;
        int gn = n0 + n;
        hs[n][k]  = (gn < N) ? h[(size_t)gn * 128 + k]  : 0.0f;
        nas[n][k] = (gn < N) ? na[(size_t)gn * 128 + k] : 0.0f;
    }
    __syncthreads();
    int j = tid;
    float accP[16], accQ[16];
#pragma unroll
    for (int n = 0; n < 16; n++) { accP[n] = 0.0f; accQ[n] = 0.0f; }
    for (int k = 0; k < 128; k++) {
        float whr = cw1[(size_t)k * 128 + j];
        float whc = cw1[(size_t)(128 + k) * 128 + j];
        float wnr = cw1[(size_t)(256 + k) * 128 + j];
        float wnc = cw1[(size_t)(384 + k) * 128 + j];
#pragma unroll
        for (int n = 0; n < 16; n++) {
            float hv = hs[n][k], nav = nas[n][k];
            accP[n] = fmaf(hv, whr, fmaf(nav, wnr, accP[n]));
            accQ[n] = fmaf(hv, whc, fmaf(nav, wnc, accQ[n]));
        }
    }
#pragma unroll
    for (int n = 0; n < 16; n++) {
        int gn = n0 + n;
        if (gn < N) {
            g_P[(size_t)gn * 128 + j] = accP[n];
            g_Q[(size_t)gn * 128 + j] = accQ[n];
        }
    }
}

// ===================== kernel 2: weight prep (transpose + fp16) =====================
__global__ void prep_weights(const float* __restrict__ cw2,
                             const float* __restrict__ pw2,
                             const float* __restrict__ sw,
                             const float* __restrict__ pw1)
{
    int idx = blockIdx.x * 256 + threadIdx.x;
    if (idx < 3 * 16384) {
        int m = idx / 16384, r = idx % 16384;
        int k = r >> 7, n = r & 127;
        const float* W = (m == 0) ? cw2 : ((m == 1) ? pw2 : sw);
        float w = W[(size_t)k * 128 + n];
        ((__half*)(g_wb + m * 34816))[n * 136 + k] = __float2half_rn(w);
    } else if (idx < 3 * 16384 + 4096) {
        int r = idx - 3 * 16384;
        int k = r >> 7, n = r & 127;   // k in 0..31
        float w = (k < 20) ? pw1[(size_t)k * 128 + n] : 0.0f;
        ((__half*)(g_wb + WB_WP1))[n * 40 + k] = __float2half_rn(w);
    }
}

// ===================== kernel 3: persistent HMMA edge kernel =====================
__global__ __launch_bounds__(THREADS, 1) void edge_hmma_kernel(
    const float* __restrict__ coord, const float* __restrict__ nvecs,
    const float* __restrict__ cb1g,  const float* __restrict__ cb2g,
    const float* __restrict__ pb1g,  const float* __restrict__ pb2g,
    const float* __restrict__ sbg,   const float* __restrict__ awg,
    const float* __restrict__ abg,
    const void* __restrict__ edges, int E,
    float* __restrict__ out)
{
    extern __shared__ __align__(16) unsigned char smem[];
    const uint32_t sb0 = smem_u32(smem);
    const int tid = threadIdx.x;
    const int wid = tid >> 5, lane = tid & 31;
    const int mw = wid & 1, nw = wid >> 1;

    // weight blob -> smem
    {
        const uint4* src = (const uint4*)g_wb;
        uint4* dst = (uint4*)smem;
        for (int i = tid; i < WBLOB_BYTES / 16; i += THREADS) dst[i] = src[i];
    }
    float* cb1s = (float*)(smem + SM_CB1);
    float* cb2s = (float*)(smem + SM_CB2);
    float* pb1s = (float*)(smem + SM_PB1);
    float* pb2s = (float*)(smem + SM_PB2);
    float* sbs  = (float*)(smem + SM_SB);
    float* aws  = (float*)(smem + SM_AW);
    float* attPs= (float*)(smem + SM_ATT);
    int*   rows = (int*)(smem + SM_ROWS);
    int*   cols = (int*)(smem + SM_COLS);
    __half* PH = (__half*)(smem + SM_PHI);
    __half* PL = (__half*)(smem + SM_PLO);
    if (tid < 128) {
        cb1s[tid] = cb1g[tid]; cb2s[tid] = cb2g[tid];
        pb1s[tid] = pb1g[tid]; pb2s[tid] = pb2g[tid];
        sbs[tid]  = sbg[tid];  aws[tid]  = awg[tid];
    }
    if (tid == 0) *(float*)(smem + SM_AB) = abg[0];
    // zero bufP pad (k 20..31) once -- never written by geometry
    for (int idx = tid; idx < TE * 12; idx += THREADS) {
        int e = idx / 12, k = 20 + idx % 12;
        PH[e * 40 + k] = __float2half_rn(0.0f);
        PL[e * 40 + k] = __float2half_rn(0.0f);
    }
    const int is64 = g_is64;
    __syncthreads();
    const float abv = *(float*)(smem + SM_AB);

    const size_t chemO = (size_t)E * 128;
    const size_t posO  = (size_t)E * 256;
    const size_t cdO   = (size_t)E * 384;

    const int nTiles = (E + TE - 1) / TE;
    for (int t = blockIdx.x; t < nTiles; t += gridDim.x) {
        const int base = t * TE;

        // ---- Phase A: geometry -> bufP (fp16 hi/lo), rows/cols, cd ----
        {
            const int e = tid & 63, g = tid >> 6;
            const int ge = base + e;
            int r = 0, c = 0;
            if (ge < E) {
                if (is64) {
                    const long long* p = (const long long*)edges;
                    r = (int)p[ge]; c = (int)p[(size_t)E + ge];
                } else {
                    const int* p = (const int*)edges;
                    r = p[ge]; c = p[(size_t)E + ge];
                }
            }
            if (g == 0) { rows[e] = r; cols[e] = c; }
            float dx = coord[r * 3 + 0] - coord[c * 3 + 0];
            float dy = coord[r * 3 + 1] - coord[c * 3 + 1];
            float dz = coord[r * 3 + 2] - coord[c * 3 + 2];
            float nrm = sqrtf(dx * dx + dy * dy + dz * dz);
            float inv = __fdividef(1.0f, nrm + 1e-8f);
            float cx = dx * inv, cy = dy * inv, cz = dz * inv;
            if (g == 0 && ge < E) {
                out[cdO + (size_t)ge * 3 + 0] = cx;
                out[cdO + (size_t)ge * 3 + 1] = cy;
                out[cdO + (size_t)ge * 3 + 2] = cz;
            }
            float ir = cx * cx + cy * cy + cz * cz;
#pragma unroll
            for (int s = 0; s < 4; s++) {
                int idx = g * 4 + s;
                if (idx < 15) {
                    float v = __expf(ir * c_scales[idx]);
                    __half hh = __float2half_rn(v);
                    PH[e * 40 + 5 + idx] = hh;
                    PL[e * 40 + 5 + idx] = __float2half_rn(v - __half2float(hh));
                }
            }
            // nprod: group g does k2=g; group 0 also k2=4
            for (int rep = 0; rep < 2; rep++) {
                int k2 = (rep == 0) ? g : 4;
                if (rep == 1 && g != 0) break;
                const float* av = &nvecs[((size_t)r * 5 + k2) * 3];
                const float* bv = &nvecs[((size_t)c * 5 + k2) * 3];
                float v = av[0] * bv[0] + av[1] * bv[1] + av[2] * bv[2];
                __half hh = __float2half_rn(v);
                PH[e * 40 + k2] = hh;
                PL[e * 40 + k2] = __float2half_rn(v - __half2float(hh));
            }
        }
        __syncthreads();   // S1

        // ---- Phase B: a1 = silu(P[r]+Q[c]+cb1) -> bufA hi/lo ----
        {
            const int e = tid >> 2;
            const int k0 = (tid & 3) * 32;
            const int r = rows[e], c = cols[e];
            const float* Pr = g_P + (size_t)r * 128;
            const float* Qc = g_Q + (size_t)c * 128;
            __half2* AH = (__half2*)(smem + SM_AHI + e * 272 + k0 * 2);
            __half2* AL = (__half2*)(smem + SM_ALO + e * 272 + k0 * 2);
#pragma unroll
            for (int j = 0; j < 32; j += 2) {
                float2 p = *(const float2*)(Pr + k0 + j);
                float2 q = *(const float2*)(Qc + k0 + j);
                float v0 = siluf(p.x + q.x + cb1s[k0 + j]);
                float v1 = siluf(p.y + q.y + cb1s[k0 + j + 1]);
                __half h0 = __float2half_rn(v0), h1 = __float2half_rn(v1);
                AH[j >> 1] = __halves2half2(h0, h1);
                AL[j >> 1] = __halves2half2(__float2half_rn(v0 - __half2float(h0)),
                                            __float2half_rn(v1 - __half2float(h1)));
            }
        }
        __syncthreads();   // S2

        // ---- GEMMs: u1_pre (posin@pw1) and chem_pre (a1@cw2) ----
        float accU[8][4], accC[8][4];
#pragma unroll
        for (int f = 0; f < 8; f++)
#pragma unroll
            for (int q = 0; q < 4; q++) { accU[f][q] = 0.0f; accC[f][q] = 0.0f; }
        gemm_tile(sb0 + SM_PHI, sb0 + SM_PLO, 80, sb0 + SM_WP1, 80, 2, mw, nw, lane, accU);
        gemm_tile(sb0 + SM_AHI, sb0 + SM_ALO, 272, sb0 + SM_WC, 272, 8, mw, nw, lane, accC);
        __syncthreads();   // S3: all bufA reads done

        // ---- Epilogue A: chem -> gmem + bufA; u1 -> bufU ----
#pragma unroll
        for (int mi = 0; mi < 2; mi++)
#pragma unroll
            for (int ni = 0; ni < 4; ni++) {
                float* cc_ = accC[mi * 4 + ni];
                float* cu_ = accU[mi * 4 + ni];
                int rrow = mw * 32 + mi * 16 + (lane >> 2);
                int cc = nw * 32 + ni * 8 + 2 * (lane & 3);
                float v00 = siluf(cc_[0] + cb2s[cc]);
                float v01 = siluf(cc_[1] + cb2s[cc + 1]);
                float v10 = siluf(cc_[2] + cb2s[cc]);
                float v11 = siluf(cc_[3] + cb2s[cc + 1]);
                int ge0 = base + rrow, ge1 = base + rrow + 8;
                if (ge0 < E) *(float2*)(out + chemO + (size_t)ge0 * 128 + cc) = make_float2(v00, v01);
                if (ge1 < E) *(float2*)(out + chemO + (size_t)ge1 * 128 + cc) = make_float2(v10, v11);
                __half h;
                h = __float2half_rn(v00);
                *(__half2*)(smem + SM_AHI + rrow * 272 + cc * 2) = __halves2half2(h, __float2half_rn(v01));
                *(__half2*)(smem + SM_ALO + rrow * 272 + cc * 2) =
                    __halves2half2(__float2half_rn(v00 - __half2float(h)),
                                   __float2half_rn(v01 - __half2float(__float2half_rn(v01))));
                h = __float2half_rn(v10);
                *(__half2*)(smem + SM_AHI + (rrow + 8) * 272 + cc * 2) = __halves2half2(h, __float2half_rn(v11));
                *(__half2*)(smem + SM_ALO + (rrow + 8) * 272 + cc * 2) =
                    __halves2half2(__float2half_rn(v10 - __half2float(h)),
                                   __float2half_rn(v11 - __half2float(__float2half_rn(v11))));
                // u1
                float u00 = siluf(cu_[0] + pb1s[cc]);
                float u01 = siluf(cu_[1] + pb1s[cc + 1]);
                float u10 = siluf(cu_[2] + pb1s[cc]);
                float u11 = siluf(cu_[3] + pb1s[cc + 1]);
                h = __float2half_rn(u00);
                *(__half2*)(smem + SM_UHI + rrow * 272 + cc * 2) = __halves2half2(h, __float2half_rn(u01));
                *(__half2*)(smem + SM_ULO + rrow * 272 + cc * 2) =
                    __halves2half2(__float2half_rn(u00 - __half2float(h)),
                                   __float2half_rn(u01 - __half2float(__float2half_rn(u01))));
                h = __float2half_rn(u10);
                *(__half2*)(smem + SM_UHI + (rrow + 8) * 272 + cc * 2) = __halves2half2(h, __float2half_rn(u11));
                *(__half2*)(smem + SM_ULO + (rrow + 8) * 272 + cc * 2) =
                    __halves2half2(__float2half_rn(u10 - __half2float(h)),
                                   __float2half_rn(u11 - __half2float(__float2half_rn(u11))));
            }
        __syncthreads();   // S4a

        // ---- GEMMs: pos (u1@pw2) and gate (chem@sw) ----
        float accP8[8][4], accG[8][4];
#pragma unroll
        for (int f = 0; f < 8; f++)
#pragma unroll
            for (int q = 0; q < 4; q++) { accP8[f][q] = 0.0f; accG[f][q] = 0.0f; }
        gemm_tile(sb0 + SM_UHI, sb0 + SM_ULO, 272, sb0 + SM_WP2, 272, 8, mw, nw, lane, accP8);
        gemm_tile(sb0 + SM_AHI, sb0 + SM_ALO, 272, sb0 + SM_WS, 272, 8, mw, nw, lane, accG);

        // ---- Epilogue B ----
        float rs[4] = {0.0f, 0.0f, 0.0f, 0.0f};
#pragma unroll
        for (int mi = 0; mi < 2; mi++)
#pragma unroll
            for (int ni = 0; ni < 4; ni++) {
                float* cp = accP8[mi * 4 + ni];
                float* cg = accG[mi * 4 + ni];
                int rrow = mw * 32 + mi * 16 + (lane >> 2);
                int cc = nw * 32 + ni * 8 + 2 * (lane & 3);
                float p00 = siluf(cp[0] + pb2s[cc]);
                float p01 = siluf(cp[1] + pb2s[cc + 1]);
                float p10 = siluf(cp[2] + pb2s[cc]);
                float p11 = siluf(cp[3] + pb2s[cc + 1]);
                int ge0 = base + rrow, ge1 = base + rrow + 8;
                if (ge0 < E) *(float2*)(out + posO + (size_t)ge0 * 128 + cc) = make_float2(p00, p01);
                if (ge1 < E) *(float2*)(out + posO + (size_t)ge1 * 128 + cc) = make_float2(p10, p11);
                float g00 = siluf(cg[0] + sbs[cc])     * p00;
                float g01 = siluf(cg[1] + sbs[cc + 1]) * p01;
                float g10 = siluf(cg[2] + sbs[cc])     * p10;
                float g11 = siluf(cg[3] + sbs[cc + 1]) * p11;
                cg[0] = g00; cg[1] = g01; cg[2] = g10; cg[3] = g11;
                rs[mi * 2 + 0] += g00 * aws[cc] + g01 * aws[cc + 1];
                rs[mi * 2 + 1] += g10 * aws[cc] + g11 * aws[cc + 1];
            }
#pragma unroll
        for (int s = 0; s < 4; s++) {
            rs[s] += __shfl_xor_sync(0xffffffffu, rs[s], 1);
            rs[s] += __shfl_xor_sync(0xffffffffu, rs[s], 2);
        }
        if ((lane & 3) == 0) {
#pragma unroll
            for (int s = 0; s < 4; s++) {
                int row = mw * 32 + (s >> 1) * 16 + (lane >> 2) + (s & 1) * 8;
                attPs[nw * 64 + row] = rs[s];
            }
        }
        __syncthreads();   // S4b
        float attv[4];
#pragma unroll
        for (int s = 0; s < 4; s++) {
            int row = mw * 32 + (s >> 1) * 16 + (lane >> 2) + (s & 1) * 8;
            attv[s] = sigmoidf(attPs[row] + attPs[64 + row] + attPs[128 + row] +
                               attPs[192 + row] + abv);
        }
#pragma unroll
        for (int mi = 0; mi < 2; mi++)
#pragma unroll
            for (int ni = 0; ni < 4; ni++) {
                float* cg = accG[mi * 4 + ni];
                int rrow = mw * 32 + mi * 16 + (lane >> 2);
                int cc = nw * 32 + ni * 8 + 2 * (lane & 3);
                int ge0 = base + rrow, ge1 = base + rrow + 8;
                float a0 = attv[mi * 2 + 0], a1 = attv[mi * 2 + 1];
                if (ge0 < E) *(float2*)(out + (size_t)ge0 * 128 + cc) =
                    make_float2(cg[0] * a0, cg[1] * a0);
                if (ge1 < E) *(float2*)(out + (size_t)ge1 * 128 + cc) =
                    make_float2(cg[2] * a1, cg[3] * a1);
            }
        __syncthreads();   // S_end
    }
}

// ===================== launch =====================
extern "C" void kernel_launch(void* const* d_in, const int* in_sizes, int n_in,
                              void* d_out, int out_size) {
    const float* h     = (const float*)d_in[0];
    const float* coord = (const float*)d_in[1];
    const float* nvecs = (const float*)d_in[2];
    const float* na    = (const float*)d_in[3];
    const float* cw1   = (const float*)d_in[4];
    const float* cb1   = (const float*)d_in[5];
    const float* cw2   = (const float*)d_in[6];
    const float* cb2   = (const float*)d_in[7];
    const float* pw1   = (const float*)d_in[8];
    const float* pb1   = (const float*)d_in[9];
    const float* pw2   = (const float*)d_in[10];
    const float* pb2   = (const float*)d_in[11];
    const float* sw    = (const float*)d_in[12];
    const float* sb    = (const float*)d_in[13];
    const float* aw    = (const float*)d_in[14];
    const float* ab    = (const float*)d_in[15];
    const void*  edges = d_in[16];

    const int N = in_sizes[0] / NF;
    const int E = out_size / 387;   // out, chem, pos (128 each) + cd (3)
    float* out = (float*)d_out;

    cudaFuncSetAttribute(edge_hmma_kernel,
                         cudaFuncAttributeMaxDynamicSharedMemorySize, SMEM_BYTES);

    int nprobe = (E < 1024) ? E : 1024;
    detect_kernel<<<1, 256>>>((const int*)edges, nprobe);
    prep_weights<<<(3 * 16384 + 4096 + 255) / 256, 256>>>(cw2, pw2, sw, pw1);
    node_pre<<<(N + 15) / 16, 128>>>(h, na, cw1, N);

    const int nTiles = (E + TE - 1) / TE;
    const int grid = nTiles < 148 ? nTiles : 148;
    edge_hmma_kernel<<<grid, THREADS, SMEM_BYTES>>>(
        coord, nvecs, cb1, cb2, pb1, pb2, sb, aw, ab, edges, E, out);
}